// round 6
// baseline (speedup 1.0000x reference)
#include <cuda_runtime.h>

// PlaneValidator: symmetric-chamfer between 1024 points and their per-plane
// reflections, then per-batch conf ranking + angular NMS.  Single fused kernel:
// last-arriving block performs the (warp-parallel) finalization.
//
//  - D[n,m] = |p_n - r_m|^2 is SYMMETRIC (reflection = involutive isometry),
//    so sde = 2 * mean_n min_m D.
//  - min_m (P2[n] + R2[m] - 2 p_n.r_m) = P2[n] + min_m (R2[m] - 2 p_n.r_m).
//  - 512 thr/block, 1 row/thread: 4 warps/SMSP for latency hiding;
//    inner loop 1 LDS.128 + 3 FFMA + 1 FMNMX per pair, dual min accumulators.

#define NB 4
#define NPTS 1024
#define NH 16
#define THREADS 512
#define ROW_CHUNK 512           // 2 chunks per (b,h); 1 row per thread
#define NBLOCKS (NB * NH * 2)   // 128

#define COS_THR 0.8660254037844387f
#define FULL 0xFFFFFFFFu

__device__ float g_part[NBLOCKS];   // per-block partial sums (rewritten every launch)
__device__ int   g_count = 0;       // arrival counter (self-resetting)

__global__ __launch_bounds__(THREADS, 1) void plane_validator_kernel(
        const float* __restrict__ pts, const float* __restrict__ ypred,
        const int* __restrict__ thr_ptr, float* __restrict__ out) {
    const int bid = blockIdx.x;
    const int bh  = bid >> 1;          // (b,h) pair
    const int rc  = bid & 1;           // row chunk
    const int t   = threadIdx.x;

    // ---------------- chamfer phase ----------------
    const float* yp = ypred + bh * 4;
    const float nx = yp[0], ny = yp[1], nz = yp[2], dpl = yp[3];
    const float inv = 1.0f / sqrtf(nx * nx + ny * ny + nz * nz);
    const float nhx = nx * inv, nhy = ny * inv, nhz = nz * inv;
    const float dh  = dpl * inv;

    const float* pb = pts + (bh >> 4) * (NPTS * 3);

    // Stage columns: reflections as float4(-2rx, -2ry, -2rz, |r|^2)
    __shared__ float4 sB[NPTS];
    for (int i = t; i < NPTS; i += THREADS) {
        float px = pb[i * 3 + 0], py = pb[i * 3 + 1], pz = pb[i * 3 + 2];
        float proj = fmaf(px, nhx, fmaf(py, nhy, fmaf(pz, nhz, dh)));
        float s = -2.0f * proj;
        float rx = fmaf(s, nhx, px);
        float ry = fmaf(s, nhy, py);
        float rz = fmaf(s, nhz, pz);
        float r2 = fmaf(rx, rx, fmaf(ry, ry, rz * rz));
        sB[i] = make_float4(-2.0f * rx, -2.0f * ry, -2.0f * rz, r2);
    }

    // This thread's row (plain point) + squared norm
    const int r = rc * ROW_CHUNK + t;
    const float ax = pb[r * 3 + 0], ay = pb[r * 3 + 1], az = pb[r * 3 + 2];
    const float p2 = fmaf(ax, ax, fmaf(ay, ay, az * az));
    __syncthreads();

    // e_m = R2[m] - 2 p.r_m ; row-min of D = p2 + min e.
    // Dual accumulators (even/odd m) halve the serial FMNMX chain.
    float ba = 3.4e38f, bb = 3.4e38f;
#pragma unroll 8
    for (int m = 0; m < NPTS; m += 2) {
        float4 q0 = sB[m];
        float4 q1 = sB[m + 1];
        float ea = fmaf(ax, q0.x, fmaf(ay, q0.y, fmaf(az, q0.z, q0.w)));
        float eb = fmaf(ax, q1.x, fmaf(ay, q1.y, fmaf(az, q1.z, q1.w)));
        ba = fminf(ba, ea);
        bb = fminf(bb, eb);
    }
    float acc = fminf(ba, bb) + p2;

#pragma unroll
    for (int o = 16; o > 0; o >>= 1)
        acc += __shfl_down_sync(FULL, acc, o);

    __shared__ float wsum[THREADS / 32];
    __shared__ int s_last;
    if ((t & 31) == 0) wsum[t >> 5] = acc;
    __syncthreads();
    if (t == 0) {
        float s = 0.0f;
#pragma unroll
        for (int i = 0; i < THREADS / 32; i++) s += wsum[i];
        g_part[bid] = s;                         // raw sum of 512 row-mins
        __threadfence();                         // publish before arrival
        int old = atomicAdd(&g_count, 1);
        s_last = (old == NBLOCKS - 1);
        if (old == NBLOCKS - 1) g_count = 0;     // reset for next graph replay
    }
    __syncthreads();
    if (!s_last) return;

    // ---------------- finalize phase (last block only; lanes 0..63) ----------------
    __shared__ float s_ex[8][64];   // exchange: nx,ny,nz,px,py,pz,cf,sd by sorted pos

    const int l = t;
    float v_nx = 0, v_ny = 0, v_nz = 0, v_px = 0, v_py = 0, v_pz = 0, v_cf = 0, v_sd = 0;
    int pos = l & 15, b = l >> 4;

    if (l < 64) {
        // threshold: decode int32 vs float32 bit pattern defensively
        int tv = thr_ptr[0];
        float tf = __int_as_float(tv);
        float thr = (tf >= 1e-6f && tf <= 1e9f) ? tf : (float)tv;

        const float* yq = ypred + l * 4;
        float qx = yq[0], qy = yq[1], qz = yq[2], qd = yq[3];
        float qi = 1.0f / sqrtf(qx * qx + qy * qy + qz * qz);
        v_nx = qx * qi; v_ny = qy * qi; v_nz = qz * qi;
        float qdh = qd * qi;
        v_px = -qdh * v_nx; v_py = -qdh * v_ny; v_pz = -qdh * v_nz;

        // sde = 2 * mean(row mins): combine the two chunk partials
        volatile float* gp = g_part;
        v_sd = (gp[2 * l] + gp[2 * l + 1]) * (2.0f / (float)NPTS);

        // group min/max over 16 lanes
        float mn = v_sd, mx = v_sd;
#pragma unroll
        for (int o = 8; o > 0; o >>= 1) {
            mn = fminf(mn, __shfl_xor_sync(FULL, mn, o, 16));
            mx = fmaxf(mx, __shfl_xor_sync(FULL, mx, o, 16));
        }
        v_cf = 1.0f - (v_sd - mn) / (mx - mn);

        // stable descending rank (== stable argsort(-cf))
        int rank = 0;
#pragma unroll
        for (int j = 0; j < NH; j++) {
            float cfj = __shfl_sync(FULL, v_cf, j, 16);
            rank += (cfj > v_cf) || (cfj == v_cf && j < pos);
        }
        int slot = b * NH + rank;
        s_ex[0][slot] = v_nx; s_ex[1][slot] = v_ny; s_ex[2][slot] = v_nz;
        s_ex[3][slot] = v_px; s_ex[4][slot] = v_py; s_ex[5][slot] = v_pz;
        s_ex[6][slot] = v_cf; s_ex[7][slot] = v_sd;
        v_cf = thr;  // carry thr across the barrier
    }
    __syncthreads();
    if (l >= 64) return;

    float thr = v_cf;
    v_nx = s_ex[0][l]; v_ny = s_ex[1][l]; v_nz = s_ex[2][l];
    v_px = s_ex[3][l]; v_py = s_ex[4][l]; v_pz = s_ex[5][l];
    v_cf = s_ex[6][l]; v_sd = s_ex[7][l];

    // sequential NMS over sorted positions, live keep bits
    int keep = (v_sd <= thr);
#pragma unroll
    for (int i = 0; i < NH; i++) {
        int   ki  = __shfl_sync(FULL, keep, i, 16);
        float inx = __shfl_sync(FULL, v_nx, i, 16);
        float iny = __shfl_sync(FULL, v_ny, i, 16);
        float inz = __shfl_sync(FULL, v_nz, i, 16);
        float dt = inx * v_nx + iny * v_ny + inz * v_nz;
        if (ki && pos > i && dt > COS_THR) keep = 0;
    }

    // stable partition destination: kept first (in order), dropped after (in order)
    unsigned ball = __ballot_sync(FULL, keep);
    unsigned seg = (ball >> (l & 16)) & 0xFFFFu;
    int kept_before = __popc(seg & ((1u << pos) - 1));
    int total_kept  = __popc(seg);
    int dest = keep ? kept_before : total_kept + (pos - kept_before);

    float* o = out + (b * NH + dest) * 8;
    float4 r0 = keep ? make_float4(v_nx, v_ny, v_nz, v_px) : make_float4(0, 0, 0, 0);
    float4 r1 = keep ? make_float4(v_py, v_pz, v_cf, v_sd) : make_float4(0, 0, 0, 0);
    ((float4*)o)[0] = r0;
    ((float4*)o)[1] = r1;
}

extern "C" void kernel_launch(void* const* d_in, const int* in_sizes, int n_in,
                              void* d_out, int out_size) {
    const float* pts = nullptr;    // 12288 elems
    const float* ypred = nullptr;  // 256 elems
    const int* thr = nullptr;      // 1 elem
    for (int i = 0; i < n_in; i++) {
        if (in_sizes[i] == NB * NPTS * 3)    pts   = (const float*)d_in[i];
        else if (in_sizes[i] == NB * NH * 4) ypred = (const float*)d_in[i];
        else if (in_sizes[i] == 1)           thr   = (const int*)d_in[i];
    }
    float* out = (float*)d_out;

    plane_validator_kernel<<<NBLOCKS, THREADS>>>(pts, ypred, thr, out);
}

// round 7
// speedup vs baseline: 1.2652x; 1.2652x over previous
#include <cuda_runtime.h>

// PlaneValidator: symmetric-chamfer between 1024 points and their per-plane
// reflections, then per-batch conf ranking + angular NMS.  Single fused kernel:
// last-arriving block performs the (warp-parallel) finalization.
//
//  - D[n,m] = |p_n - r_m|^2 is SYMMETRIC (reflection = involutive isometry),
//    so sde = 2 * mean_n min_m D.
//  - min_m (P2[n] + R2[m] - 2 p_n.r_m) = P2[n] + min_m (R2[m] - 2 p_n.r_m).
//  - Inner loop: POINTS paired into f32x2 lanes (rows stay independent chains):
//    per 2 points x 2 rows = 2 LDS.128 + 6 FFMA2 + 4 FMNMX.  Same LDS/point
//    as scalar version, half the fma-pipe occupancy (3-reg FFMA rt=2/SMSP).

#define NB 4
#define NPTS 1024
#define NH 16
#define THREADS 256
#define ROW_CHUNK 512           // 2 chunks per (b,h); 2 rows per thread
#define NBLOCKS (NB * NH * 2)   // 128

#define COS_THR 0.8660254037844387f
#define FULL 0xFFFFFFFFu

__device__ float g_part[NBLOCKS];   // per-block partial sums (rewritten every launch)
__device__ int   g_count = 0;       // arrival counter (self-resetting)

__device__ __forceinline__ unsigned long long fma2(
        unsigned long long a, unsigned long long b, unsigned long long c) {
    unsigned long long d;
    asm("fma.rn.f32x2 %0, %1, %2, %3;" : "=l"(d) : "l"(a), "l"(b), "l"(c));
    return d;
}
__device__ __forceinline__ unsigned long long pack2(float lo, float hi) {
    unsigned long long d;
    asm("mov.b64 %0, {%1, %2};" : "=l"(d) : "f"(lo), "f"(hi));
    return d;
}
__device__ __forceinline__ void unpack2(unsigned long long v, float& lo, float& hi) {
    asm("mov.b64 {%0, %1}, %2;" : "=f"(lo), "=f"(hi) : "l"(v));
}

__global__ __launch_bounds__(THREADS, 1) void plane_validator_kernel(
        const float* __restrict__ pts, const float* __restrict__ ypred,
        const int* __restrict__ thr_ptr, float* __restrict__ out) {
    const int bid = blockIdx.x;
    const int bh  = bid >> 1;          // (b,h) pair
    const int rc  = bid & 1;           // row chunk
    const int t   = threadIdx.x;

    // ---------------- chamfer phase ----------------
    const float* yp = ypred + bh * 4;
    const float nx = yp[0], ny = yp[1], nz = yp[2], dpl = yp[3];
    const float inv = 1.0f / sqrtf(nx * nx + ny * ny + nz * nz);
    const float nhx = nx * inv, nhy = ny * inv, nhz = nz * inv;
    const float dh  = dpl * inv;

    const float* pb = pts + (bh >> 4) * (NPTS * 3);

    // Column tile, point-PAIR packed:
    //   sB[2k]   = { {-2rx_m,-2rx_m1}, {-2ry_m,-2ry_m1} }
    //   sB[2k+1] = { {-2rz_m,-2rz_m1}, { r2_m , r2_m1 } }   (m=2k, m1=2k+1)
    // 16 B/point, one LDS.128 per point per warp (broadcast) — same as scalar.
    __shared__ ulonglong2 sB[NPTS];     // 16 KB
    for (int k = t; k < NPTS / 2; k += THREADS) {
        float rx[2], ry[2], rz[2], r2[2];
#pragma unroll
        for (int j = 0; j < 2; j++) {
            int i = 2 * k + j;
            float px = pb[i * 3 + 0], py = pb[i * 3 + 1], pz = pb[i * 3 + 2];
            float proj = fmaf(px, nhx, fmaf(py, nhy, fmaf(pz, nhz, dh)));
            float s = -2.0f * proj;
            rx[j] = fmaf(s, nhx, px);
            ry[j] = fmaf(s, nhy, py);
            rz[j] = fmaf(s, nhz, pz);
            r2[j] = fmaf(rx[j], rx[j], fmaf(ry[j], ry[j], rz[j] * rz[j]));
        }
        sB[2 * k]     = make_ulonglong2(pack2(-2.0f * rx[0], -2.0f * rx[1]),
                                        pack2(-2.0f * ry[0], -2.0f * ry[1]));
        sB[2 * k + 1] = make_ulonglong2(pack2(-2.0f * rz[0], -2.0f * rz[1]),
                                        pack2(r2[0], r2[1]));
    }

    // This thread's 2 rows (plain points): coords broadcast into both f32x2 lanes
    float p2[2];
    unsigned long long ax2[2], ay2[2], az2[2];
#pragma unroll
    for (int kk = 0; kk < 2; kk++) {
        int r = rc * ROW_CHUNK + kk * THREADS + t;
        float px = pb[r * 3 + 0], py = pb[r * 3 + 1], pz = pb[r * 3 + 2];
        ax2[kk] = pack2(px, px);
        ay2[kk] = pack2(py, py);
        az2[kk] = pack2(pz, pz);
        p2[kk] = fmaf(px, px, fmaf(py, py, pz * pz));
    }
    __syncthreads();

    // e_{m,m+1} = {R2 - 2 p.r} for both points at once, per row.
    // 4 min accumulators (row x lane) keep the FMNMX chains short & independent.
    float b0a = 3.4e38f, b0b = 3.4e38f, b1a = 3.4e38f, b1b = 3.4e38f;
#pragma unroll 8
    for (int k = 0; k < NPTS / 2; k++) {
        ulonglong2 u0 = sB[2 * k];       // {xx, yy}
        ulonglong2 u1 = sB[2 * k + 1];   // {zz, rr}
        unsigned long long e0 = fma2(ax2[0], u0.x,
                                fma2(ay2[0], u0.y,
                                fma2(az2[0], u1.x, u1.y)));
        unsigned long long e1 = fma2(ax2[1], u0.x,
                                fma2(ay2[1], u0.y,
                                fma2(az2[1], u1.x, u1.y)));
        float e0lo, e0hi, e1lo, e1hi;
        unpack2(e0, e0lo, e0hi);
        unpack2(e1, e1lo, e1hi);
        b0a = fminf(b0a, e0lo);
        b0b = fminf(b0b, e0hi);
        b1a = fminf(b1a, e1lo);
        b1b = fminf(b1b, e1hi);
    }
    float acc = (fminf(b0a, b0b) + p2[0]) + (fminf(b1a, b1b) + p2[1]);

#pragma unroll
    for (int o = 16; o > 0; o >>= 1)
        acc += __shfl_down_sync(FULL, acc, o);

    __shared__ float wsum[THREADS / 32];
    __shared__ int s_last;
    if ((t & 31) == 0) wsum[t >> 5] = acc;
    __syncthreads();
    if (t == 0) {
        float s = 0.0f;
#pragma unroll
        for (int i = 0; i < THREADS / 32; i++) s += wsum[i];
        g_part[bid] = s;                         // raw sum of 512 row-mins
        __threadfence();                         // publish before arrival
        int old = atomicAdd(&g_count, 1);
        s_last = (old == NBLOCKS - 1);
        if (old == NBLOCKS - 1) g_count = 0;     // reset for next graph replay
    }
    __syncthreads();
    if (!s_last) return;

    // ---------------- finalize phase (last block only; lanes 0..63) ----------------
    __shared__ float s_ex[8][64];   // exchange: nx,ny,nz,px,py,pz,cf,sd by sorted pos

    const int l = t;
    float v_nx = 0, v_ny = 0, v_nz = 0, v_px = 0, v_py = 0, v_pz = 0, v_cf = 0, v_sd = 0;
    int pos = l & 15, b = l >> 4;

    if (l < 64) {
        // threshold: decode int32 vs float32 bit pattern defensively
        int tv = thr_ptr[0];
        float tf = __int_as_float(tv);
        float thr = (tf >= 1e-6f && tf <= 1e9f) ? tf : (float)tv;

        const float* yq = ypred + l * 4;
        float qx = yq[0], qy = yq[1], qz = yq[2], qd = yq[3];
        float qi = 1.0f / sqrtf(qx * qx + qy * qy + qz * qz);
        v_nx = qx * qi; v_ny = qy * qi; v_nz = qz * qi;
        float qdh = qd * qi;
        v_px = -qdh * v_nx; v_py = -qdh * v_ny; v_pz = -qdh * v_nz;

        // sde = 2 * mean(row mins): combine the two chunk partials
        volatile float* gp = g_part;
        v_sd = (gp[2 * l] + gp[2 * l + 1]) * (2.0f / (float)NPTS);

        // group min/max over 16 lanes
        float mn = v_sd, mx = v_sd;
#pragma unroll
        for (int o = 8; o > 0; o >>= 1) {
            mn = fminf(mn, __shfl_xor_sync(FULL, mn, o, 16));
            mx = fmaxf(mx, __shfl_xor_sync(FULL, mx, o, 16));
        }
        v_cf = 1.0f - (v_sd - mn) / (mx - mn);

        // stable descending rank (== stable argsort(-cf))
        int rank = 0;
#pragma unroll
        for (int j = 0; j < NH; j++) {
            float cfj = __shfl_sync(FULL, v_cf, j, 16);
            rank += (cfj > v_cf) || (cfj == v_cf && j < pos);
        }
        int slot = b * NH + rank;
        s_ex[0][slot] = v_nx; s_ex[1][slot] = v_ny; s_ex[2][slot] = v_nz;
        s_ex[3][slot] = v_px; s_ex[4][slot] = v_py; s_ex[5][slot] = v_pz;
        s_ex[6][slot] = v_cf; s_ex[7][slot] = v_sd;
        v_cf = thr;  // carry thr across the barrier
    }
    __syncthreads();
    if (l >= 64) return;

    float thr = v_cf;
    v_nx = s_ex[0][l]; v_ny = s_ex[1][l]; v_nz = s_ex[2][l];
    v_px = s_ex[3][l]; v_py = s_ex[4][l]; v_pz = s_ex[5][l];
    v_cf = s_ex[6][l]; v_sd = s_ex[7][l];

    // sequential NMS over sorted positions, live keep bits
    int keep = (v_sd <= thr);
#pragma unroll
    for (int i = 0; i < NH; i++) {
        int   ki  = __shfl_sync(FULL, keep, i, 16);
        float inx = __shfl_sync(FULL, v_nx, i, 16);
        float iny = __shfl_sync(FULL, v_ny, i, 16);
        float inz = __shfl_sync(FULL, v_nz, i, 16);
        float dt = inx * v_nx + iny * v_ny + inz * v_nz;
        if (ki && pos > i && dt > COS_THR) keep = 0;
    }

    // stable partition destination: kept first (in order), dropped after (in order)
    unsigned ball = __ballot_sync(FULL, keep);
    unsigned seg = (ball >> (l & 16)) & 0xFFFFu;
    int kept_before = __popc(seg & ((1u << pos) - 1));
    int total_kept  = __popc(seg);
    int dest = keep ? kept_before : total_kept + (pos - kept_before);

    float* o = out + (b * NH + dest) * 8;
    float4 r0 = keep ? make_float4(v_nx, v_ny, v_nz, v_px) : make_float4(0, 0, 0, 0);
    float4 r1 = keep ? make_float4(v_py, v_pz, v_cf, v_sd) : make_float4(0, 0, 0, 0);
    ((float4*)o)[0] = r0;
    ((float4*)o)[1] = r1;
}

extern "C" void kernel_launch(void* const* d_in, const int* in_sizes, int n_in,
                              void* d_out, int out_size) {
    const float* pts = nullptr;    // 12288 elems
    const float* ypred = nullptr;  // 256 elems
    const int* thr = nullptr;      // 1 elem
    for (int i = 0; i < n_in; i++) {
        if (in_sizes[i] == NB * NPTS * 3)    pts   = (const float*)d_in[i];
        else if (in_sizes[i] == NB * NH * 4) ypred = (const float*)d_in[i];
        else if (in_sizes[i] == 1)           thr   = (const int*)d_in[i];
    }
    float* out = (float*)d_out;

    plane_validator_kernel<<<NBLOCKS, THREADS>>>(pts, ypred, thr, out);
}

// round 8
// speedup vs baseline: 1.2741x; 1.0071x over previous
#include <cuda_runtime.h>

// PlaneValidator: symmetric-chamfer between 1024 points and their per-plane
// reflections, then per-batch conf ranking + angular NMS.  Single fused kernel:
// last-arriving block performs the (warp-parallel) finalization.
//
//  - D[n,m] = |p_n - r_m|^2 is SYMMETRIC (reflection = involutive isometry),
//    so sde = 2 * mean_n min_m D.
//  - min_m (P2[n] + R2[m] - 2 p_n.r_m) = P2[n] + min_m (R2[m] - 2 p_n.r_m).
//  - Inner loop: scalar 3 FFMA + 1 FMNMX per pair, SOFTWARE-PIPELINED:
//    ping-pong register buffers of 8 points; 8 back-to-back LDS.128 prefetch
//    the next stage while the current stage computes (hides 29-cyc LDS lat).

#define NB 4
#define NPTS 1024
#define NH 16
#define THREADS 256
#define ROW_CHUNK 512           // 2 chunks per (b,h); 2 rows per thread
#define NBLOCKS (NB * NH * 2)   // 128
#define STAGE 8                 // points per pipeline half-stage

#define COS_THR 0.8660254037844387f
#define FULL 0xFFFFFFFFu

__device__ float g_part[NBLOCKS];   // per-block partial sums (rewritten every launch)
__device__ int   g_count = 0;       // arrival counter (self-resetting)

__global__ __launch_bounds__(THREADS, 1) void plane_validator_kernel(
        const float* __restrict__ pts, const float* __restrict__ ypred,
        const int* __restrict__ thr_ptr, float* __restrict__ out) {
    const int bid = blockIdx.x;
    const int bh  = bid >> 1;          // (b,h) pair
    const int rc  = bid & 1;           // row chunk
    const int t   = threadIdx.x;

    // ---------------- chamfer phase ----------------
    const float* yp = ypred + bh * 4;
    const float nx = yp[0], ny = yp[1], nz = yp[2], dpl = yp[3];
    const float inv = 1.0f / sqrtf(nx * nx + ny * ny + nz * nz);
    const float nhx = nx * inv, nhy = ny * inv, nhz = nz * inv;
    const float dh  = dpl * inv;

    const float* pb = pts + (bh >> 4) * (NPTS * 3);

    // Columns: reflections as float4(-2rx, -2ry, -2rz, |r|^2).
    // Padded by STAGE entries: the pipeline's final prefetch reads them but
    // never computes on them (removes the guard branch from the hot loop).
    __shared__ float4 sB[NPTS + STAGE];
    for (int i = t; i < NPTS; i += THREADS) {
        float px = pb[i * 3 + 0], py = pb[i * 3 + 1], pz = pb[i * 3 + 2];
        float proj = fmaf(px, nhx, fmaf(py, nhy, fmaf(pz, nhz, dh)));
        float s = -2.0f * proj;
        float rx = fmaf(s, nhx, px);
        float ry = fmaf(s, nhy, py);
        float rz = fmaf(s, nhz, pz);
        float r2 = fmaf(rx, rx, fmaf(ry, ry, rz * rz));
        sB[i] = make_float4(-2.0f * rx, -2.0f * ry, -2.0f * rz, r2);
    }
    if (t < STAGE) sB[NPTS + t] = make_float4(0.f, 0.f, 0.f, 0.f);

    // This thread's 2 rows (plain points) + squared norms
    float ax[2], ay[2], az[2], p2[2];
#pragma unroll
    for (int k = 0; k < 2; k++) {
        int r = rc * ROW_CHUNK + k * THREADS + t;
        float px = pb[r * 3 + 0], py = pb[r * 3 + 1], pz = pb[r * 3 + 2];
        ax[k] = px; ay[k] = py; az[k] = pz;
        p2[k] = fmaf(px, px, fmaf(py, py, pz * pz));
    }
    __syncthreads();

    // e_m = R2[m] - 2 p.r_m ; row-min of D = p2 + min e.
    // 4 min accumulators (2 rows x even/odd point) keep FMNMX chains short.
    float b0a = 3.4e38f, b0b = 3.4e38f, b1a = 3.4e38f, b1b = 3.4e38f;

    float4 qA[STAGE], qB[STAGE];
#pragma unroll
    for (int j = 0; j < STAGE; j++) qA[j] = sB[j];          // prologue fill

#define COMPUTE_STAGE(Q)                                                       \
    _Pragma("unroll")                                                          \
    for (int j = 0; j < STAGE; j++) {                                          \
        float4 q = Q[j];                                                       \
        float e0 = fmaf(ax[0], q.x, fmaf(ay[0], q.y, fmaf(az[0], q.z, q.w))); \
        float e1 = fmaf(ax[1], q.x, fmaf(ay[1], q.y, fmaf(az[1], q.z, q.w))); \
        if (j & 1) { b0b = fminf(b0b, e0); b1b = fminf(b1b, e1); }             \
        else       { b0a = fminf(b0a, e0); b1a = fminf(b1a, e1); }             \
    }

    for (int k = 0; k < NPTS; k += 2 * STAGE) {
#pragma unroll
        for (int j = 0; j < STAGE; j++) qB[j] = sB[k + STAGE + j];
        COMPUTE_STAGE(qA)
#pragma unroll
        for (int j = 0; j < STAGE; j++) qA[j] = sB[k + 2 * STAGE + j];  // pad-safe
        COMPUTE_STAGE(qB)
    }
#undef COMPUTE_STAGE

    float acc = (fminf(b0a, b0b) + p2[0]) + (fminf(b1a, b1b) + p2[1]);

#pragma unroll
    for (int o = 16; o > 0; o >>= 1)
        acc += __shfl_down_sync(FULL, acc, o);

    __shared__ float wsum[THREADS / 32];
    __shared__ int s_last;
    if ((t & 31) == 0) wsum[t >> 5] = acc;
    __syncthreads();
    if (t == 0) {
        float s = 0.0f;
#pragma unroll
        for (int i = 0; i < THREADS / 32; i++) s += wsum[i];
        g_part[bid] = s;                         // raw sum of 512 row-mins
        __threadfence();                         // publish before arrival
        int old = atomicAdd(&g_count, 1);
        s_last = (old == NBLOCKS - 1);
        if (old == NBLOCKS - 1) g_count = 0;     // reset for next graph replay
    }
    __syncthreads();
    if (!s_last) return;

    // ---------------- finalize phase (last block only; lanes 0..63) ----------------
    __shared__ float s_ex[8][64];   // exchange: nx,ny,nz,px,py,pz,cf,sd by sorted pos

    const int l = t;
    float v_nx = 0, v_ny = 0, v_nz = 0, v_px = 0, v_py = 0, v_pz = 0, v_cf = 0, v_sd = 0;
    int pos = l & 15, b = l >> 4;

    if (l < 64) {
        // threshold: decode int32 vs float32 bit pattern defensively
        int tv = thr_ptr[0];
        float tf = __int_as_float(tv);
        float thr = (tf >= 1e-6f && tf <= 1e9f) ? tf : (float)tv;

        const float* yq = ypred + l * 4;
        float qx = yq[0], qy = yq[1], qz = yq[2], qd = yq[3];
        float qi = 1.0f / sqrtf(qx * qx + qy * qy + qz * qz);
        v_nx = qx * qi; v_ny = qy * qi; v_nz = qz * qi;
        float qdh = qd * qi;
        v_px = -qdh * v_nx; v_py = -qdh * v_ny; v_pz = -qdh * v_nz;

        // sde = 2 * mean(row mins): combine the two chunk partials
        volatile float* gp = g_part;
        v_sd = (gp[2 * l] + gp[2 * l + 1]) * (2.0f / (float)NPTS);

        // group min/max over 16 lanes
        float mn = v_sd, mx = v_sd;
#pragma unroll
        for (int o = 8; o > 0; o >>= 1) {
            mn = fminf(mn, __shfl_xor_sync(FULL, mn, o, 16));
            mx = fmaxf(mx, __shfl_xor_sync(FULL, mx, o, 16));
        }
        v_cf = 1.0f - (v_sd - mn) / (mx - mn);

        // stable descending rank (== stable argsort(-cf))
        int rank = 0;
#pragma unroll
        for (int j = 0; j < NH; j++) {
            float cfj = __shfl_sync(FULL, v_cf, j, 16);
            rank += (cfj > v_cf) || (cfj == v_cf && j < pos);
        }
        int slot = b * NH + rank;
        s_ex[0][slot] = v_nx; s_ex[1][slot] = v_ny; s_ex[2][slot] = v_nz;
        s_ex[3][slot] = v_px; s_ex[4][slot] = v_py; s_ex[5][slot] = v_pz;
        s_ex[6][slot] = v_cf; s_ex[7][slot] = v_sd;
        v_cf = thr;  // carry thr across the barrier
    }
    __syncthreads();
    if (l >= 64) return;

    float thr = v_cf;
    v_nx = s_ex[0][l]; v_ny = s_ex[1][l]; v_nz = s_ex[2][l];
    v_px = s_ex[3][l]; v_py = s_ex[4][l]; v_pz = s_ex[5][l];
    v_cf = s_ex[6][l]; v_sd = s_ex[7][l];

    // sequential NMS over sorted positions, live keep bits
    int keep = (v_sd <= thr);
#pragma unroll
    for (int i = 0; i < NH; i++) {
        int   ki  = __shfl_sync(FULL, keep, i, 16);
        float inx = __shfl_sync(FULL, v_nx, i, 16);
        float iny = __shfl_sync(FULL, v_ny, i, 16);
        float inz = __shfl_sync(FULL, v_nz, i, 16);
        float dt = inx * v_nx + iny * v_ny + inz * v_nz;
        if (ki && pos > i && dt > COS_THR) keep = 0;
    }

    // stable partition destination: kept first (in order), dropped after (in order)
    unsigned ball = __ballot_sync(FULL, keep);
    unsigned seg = (ball >> (l & 16)) & 0xFFFFu;
    int kept_before = __popc(seg & ((1u << pos) - 1));
    int total_kept  = __popc(seg);
    int dest = keep ? kept_before : total_kept + (pos - kept_before);

    float* o = out + (b * NH + dest) * 8;
    float4 r0 = keep ? make_float4(v_nx, v_ny, v_nz, v_px) : make_float4(0, 0, 0, 0);
    float4 r1 = keep ? make_float4(v_py, v_pz, v_cf, v_sd) : make_float4(0, 0, 0, 0);
    ((float4*)o)[0] = r0;
    ((float4*)o)[1] = r1;
}

extern "C" void kernel_launch(void* const* d_in, const int* in_sizes, int n_in,
                              void* d_out, int out_size) {
    const float* pts = nullptr;    // 12288 elems
    const float* ypred = nullptr;  // 256 elems
    const int* thr = nullptr;      // 1 elem
    for (int i = 0; i < n_in; i++) {
        if (in_sizes[i] == NB * NPTS * 3)    pts   = (const float*)d_in[i];
        else if (in_sizes[i] == NB * NH * 4) ypred = (const float*)d_in[i];
        else if (in_sizes[i] == 1)           thr   = (const int*)d_in[i];
    }
    float* out = (float*)d_out;

    plane_validator_kernel<<<NBLOCKS, THREADS>>>(pts, ypred, thr, out);
}

// round 9
// speedup vs baseline: 1.3289x; 1.0430x over previous
#include <cuda_runtime.h>

// PlaneValidator: symmetric-chamfer between 1024 points and their per-plane
// reflections, then per-batch conf ranking + angular NMS.  Single fused kernel.
//
//  - D[n,m] = |p_n - r_m|^2 is SYMMETRIC  ->  sde = 2 * mean_n min_m D.
//  - row-min of D = p2 + min_m (R2[m] - 2 p.r_m): 3 FFMA + 1 FMNMX per pair.
//  - COLUMN-SPLIT grid: 2 blocks per (b,h), each 512 columns x all 1024 rows,
//    512 threads x 2 rows/thread -> 4 warps/SMSP latency hiding at unchanged
//    LDS-per-pair.  Per-bh 2-arrival combine (min over halves), then the last
//    combiner runs the warp-parallel finalize.

#define NB 4
#define NPTS 1024
#define NH 16
#define THREADS 512
#define HALF 512                // columns per block
#define NBLOCKS (NB * NH * 2)   // 128

#define COS_THR 0.8660254037844387f
#define FULL 0xFFFFFFFFu
#define FINF 3.4e38f

__device__ float g_rowmin[NBLOCKS * NPTS];  // per-block partial row minima (+p2)
__device__ float g_part[NB * NH];           // per-bh raw sums of row minima
__device__ int   g_cnt_bh[NB * NH];         // 2-arrival counters (self-resetting)
__device__ int   g_cnt_fin = 0;             // 64-arrival counter (self-resetting)

__global__ __launch_bounds__(THREADS, 1) void plane_validator_kernel(
        const float* __restrict__ pts, const float* __restrict__ ypred,
        const int* __restrict__ thr_ptr, float* __restrict__ out) {
    const int bid = blockIdx.x;
    const int bh  = bid >> 1;          // (b,h) pair
    const int ch  = bid & 1;           // column half
    const int t   = threadIdx.x;

    // ---------------- chamfer phase ----------------
    const float* yp = ypred + bh * 4;
    const float nx = yp[0], ny = yp[1], nz = yp[2], dpl = yp[3];
    const float inv = 1.0f / sqrtf(nx * nx + ny * ny + nz * nz);
    const float nhx = nx * inv, nhy = ny * inv, nhz = nz * inv;
    const float dh  = dpl * inv;

    const float* pb = pts + (bh >> 4) * (NPTS * 3);

    // Stage this block's 512-column half: reflections as float4(-2r, |r|^2)
    __shared__ float4 sB[HALF];
    {
        int i = ch * HALF + t;
        float px = pb[i * 3 + 0], py = pb[i * 3 + 1], pz = pb[i * 3 + 2];
        float proj = fmaf(px, nhx, fmaf(py, nhy, fmaf(pz, nhz, dh)));
        float s = -2.0f * proj;
        float rx = fmaf(s, nhx, px);
        float ry = fmaf(s, nhy, py);
        float rz = fmaf(s, nhz, pz);
        float r2 = fmaf(rx, rx, fmaf(ry, ry, rz * rz));
        sB[t] = make_float4(-2.0f * rx, -2.0f * ry, -2.0f * rz, r2);
    }

    // This thread's 2 rows (plain points) + squared norms (rows t and t+512)
    float ax[2], ay[2], az[2], p2[2];
#pragma unroll
    for (int k = 0; k < 2; k++) {
        int r = k * HALF + t;
        float px = pb[r * 3 + 0], py = pb[r * 3 + 1], pz = pb[r * 3 + 2];
        ax[k] = px; ay[k] = py; az[k] = pz;
        p2[k] = fmaf(px, px, fmaf(py, py, pz * pz));
    }
    __syncthreads();

    // Partial row-min over this column half; dual accumulators per row.
    float b0a = FINF, b0b = FINF, b1a = FINF, b1b = FINF;
#pragma unroll 16
    for (int m = 0; m < HALF; m += 2) {
        float4 q0 = sB[m];
        float4 q1 = sB[m + 1];
        float e0a = fmaf(ax[0], q0.x, fmaf(ay[0], q0.y, fmaf(az[0], q0.z, q0.w)));
        float e1a = fmaf(ax[1], q0.x, fmaf(ay[1], q0.y, fmaf(az[1], q0.z, q0.w)));
        float e0b = fmaf(ax[0], q1.x, fmaf(ay[0], q1.y, fmaf(az[0], q1.z, q1.w)));
        float e1b = fmaf(ax[1], q1.x, fmaf(ay[1], q1.y, fmaf(az[1], q1.z, q1.w)));
        b0a = fminf(b0a, e0a);
        b1a = fminf(b1a, e1a);
        b0b = fminf(b0b, e0b);
        b1b = fminf(b1b, e1b);
    }
    // min(e)+p2 = min(e+p2): safe to min-combine across halves later.
    const float v0 = fminf(b0a, b0b) + p2[0];
    const float v1 = fminf(b1a, b1b) + p2[1];

    g_rowmin[bid * NPTS + t]        = v0;
    g_rowmin[bid * NPTS + HALF + t] = v1;
    __threadfence();            // each thread publishes its own stores
    __syncthreads();            // all fences done before arrival

    __shared__ int s_flag;
    if (t == 0) {
        int old = atomicAdd(&g_cnt_bh[bh], 1);
        s_flag = (old == 1);    // second arriver combines
    }
    __syncthreads();
    if (!s_flag) return;

    // ---------------- combine phase (one block per bh) ----------------
    __threadfence();            // acquire peer's published rowmins
    const int peer = bid ^ 1;
    volatile float* rm = g_rowmin;
    float pv0 = rm[peer * NPTS + t];
    float pv1 = rm[peer * NPTS + HALF + t];
    float s = fminf(v0, pv0) + fminf(v1, pv1);

#pragma unroll
    for (int o = 16; o > 0; o >>= 1)
        s += __shfl_down_sync(FULL, s, o);

    __shared__ float wsum[THREADS / 32];
    if ((t & 31) == 0) wsum[t >> 5] = s;
    __syncthreads();
    if (t == 0) {
        float tot = 0.0f;
#pragma unroll
        for (int i = 0; i < THREADS / 32; i++) tot += wsum[i];
        g_part[bh] = tot;            // raw sum of 1024 row-mins
        g_cnt_bh[bh] = 0;            // reset pair counter for next replay
        __threadfence();
        int old2 = atomicAdd(&g_cnt_fin, 1);
        s_flag = (old2 == NB * NH - 1);
        if (old2 == NB * NH - 1) g_cnt_fin = 0;   // reset for next replay
    }
    __syncthreads();
    if (!s_flag) return;

    // ---------------- finalize phase (last combiner; lanes 0..63) ----------------
    __shared__ float s_ex[8][64];   // exchange: nx,ny,nz,px,py,pz,cf,sd by sorted pos

    const int l = t;
    float v_nx = 0, v_ny = 0, v_nz = 0, v_px = 0, v_py = 0, v_pz = 0, v_cf = 0, v_sd = 0;
    int pos = l & 15, b = l >> 4;

    if (l < 64) {
        // threshold: decode int32 vs float32 bit pattern defensively
        int tv = thr_ptr[0];
        float tf = __int_as_float(tv);
        float thr = (tf >= 1e-6f && tf <= 1e9f) ? tf : (float)tv;

        const float* yq = ypred + l * 4;
        float qx = yq[0], qy = yq[1], qz = yq[2], qd = yq[3];
        float qi = 1.0f / sqrtf(qx * qx + qy * qy + qz * qz);
        v_nx = qx * qi; v_ny = qy * qi; v_nz = qz * qi;
        float qdh = qd * qi;
        v_px = -qdh * v_nx; v_py = -qdh * v_ny; v_pz = -qdh * v_nz;

        // sde = 2 * mean(row mins)   (D symmetric)
        volatile float* gp = g_part;
        v_sd = gp[l] * (2.0f / (float)NPTS);

        // group min/max over 16 lanes
        float mn = v_sd, mx = v_sd;
#pragma unroll
        for (int o = 8; o > 0; o >>= 1) {
            mn = fminf(mn, __shfl_xor_sync(FULL, mn, o, 16));
            mx = fmaxf(mx, __shfl_xor_sync(FULL, mx, o, 16));
        }
        v_cf = 1.0f - (v_sd - mn) / (mx - mn);

        // stable descending rank (== stable argsort(-cf))
        int rank = 0;
#pragma unroll
        for (int j = 0; j < NH; j++) {
            float cfj = __shfl_sync(FULL, v_cf, j, 16);
            rank += (cfj > v_cf) || (cfj == v_cf && j < pos);
        }
        int slot = b * NH + rank;
        s_ex[0][slot] = v_nx; s_ex[1][slot] = v_ny; s_ex[2][slot] = v_nz;
        s_ex[3][slot] = v_px; s_ex[4][slot] = v_py; s_ex[5][slot] = v_pz;
        s_ex[6][slot] = v_cf; s_ex[7][slot] = v_sd;
        v_cf = thr;  // carry thr across the barrier
    }
    __syncthreads();
    if (l >= 64) return;

    float thr = v_cf;
    v_nx = s_ex[0][l]; v_ny = s_ex[1][l]; v_nz = s_ex[2][l];
    v_px = s_ex[3][l]; v_py = s_ex[4][l]; v_pz = s_ex[5][l];
    v_cf = s_ex[6][l]; v_sd = s_ex[7][l];

    // sequential NMS over sorted positions, live keep bits
    int keep = (v_sd <= thr);
#pragma unroll
    for (int i = 0; i < NH; i++) {
        int   ki  = __shfl_sync(FULL, keep, i, 16);
        float inx = __shfl_sync(FULL, v_nx, i, 16);
        float iny = __shfl_sync(FULL, v_ny, i, 16);
        float inz = __shfl_sync(FULL, v_nz, i, 16);
        float dt = inx * v_nx + iny * v_ny + inz * v_nz;
        if (ki && pos > i && dt > COS_THR) keep = 0;
    }

    // stable partition destination: kept first (in order), dropped after (in order)
    unsigned ball = __ballot_sync(FULL, keep);
    unsigned seg = (ball >> (l & 16)) & 0xFFFFu;
    int kept_before = __popc(seg & ((1u << pos) - 1));
    int total_kept  = __popc(seg);
    int dest = keep ? kept_before : total_kept + (pos - kept_before);

    float* o = out + (b * NH + dest) * 8;
    float4 r0 = keep ? make_float4(v_nx, v_ny, v_nz, v_px) : make_float4(0, 0, 0, 0);
    float4 r1 = keep ? make_float4(v_py, v_pz, v_cf, v_sd) : make_float4(0, 0, 0, 0);
    ((float4*)o)[0] = r0;
    ((float4*)o)[1] = r1;
}

extern "C" void kernel_launch(void* const* d_in, const int* in_sizes, int n_in,
                              void* d_out, int out_size) {
    const float* pts = nullptr;    // 12288 elems
    const float* ypred = nullptr;  // 256 elems
    const int* thr = nullptr;      // 1 elem
    for (int i = 0; i < n_in; i++) {
        if (in_sizes[i] == NB * NPTS * 3)    pts   = (const float*)d_in[i];
        else if (in_sizes[i] == NB * NH * 4) ypred = (const float*)d_in[i];
        else if (in_sizes[i] == 1)           thr   = (const int*)d_in[i];
    }
    float* out = (float*)d_out;

    plane_validator_kernel<<<NBLOCKS, THREADS>>>(pts, ypred, thr, out);
}

// round 10
// speedup vs baseline: 1.3994x; 1.0530x over previous
#include <cuda_runtime.h>

// PlaneValidator: symmetric-chamfer between 1024 points and their per-plane
// reflections, then per-batch conf ranking + angular NMS.  Single fused kernel.
//
//  - D[n,m] = |p_n - r_m|^2 is SYMMETRIC  ->  sde = 2 * mean_n min_m D.
//  - row-min of D = p2 + min_m (R2[m] - 2 p.r_m).
//  - COLUMN-SPLIT grid (R9): 2 blocks per (b,h), 512 cols x 1024 rows each,
//    512 thr x 2 rows/thread -> 4 warps/SMSP.
//  - POINT-PAIR f32x2 packing (R7): per 2 points x 2 rows = 2 LDS.128 +
//    6 FFMA2 + 4 FMNMX  (~12 issues / 4 pairs).

#define NB 4
#define NPTS 1024
#define NH 16
#define THREADS 512
#define HALF 512                // columns per block
#define NBLOCKS (NB * NH * 2)   // 128

#define COS_THR 0.8660254037844387f
#define FULL 0xFFFFFFFFu
#define FINF 3.4e38f

__device__ float g_rowmin[NBLOCKS * NPTS];  // per-block partial row minima (+p2)
__device__ float g_part[NB * NH];           // per-bh raw sums of row minima
__device__ int   g_cnt_bh[NB * NH];         // 2-arrival counters (self-resetting)
__device__ int   g_cnt_fin = 0;             // 64-arrival counter (self-resetting)

__device__ __forceinline__ unsigned long long fma2(
        unsigned long long a, unsigned long long b, unsigned long long c) {
    unsigned long long d;
    asm("fma.rn.f32x2 %0, %1, %2, %3;" : "=l"(d) : "l"(a), "l"(b), "l"(c));
    return d;
}
__device__ __forceinline__ unsigned long long pack2(float lo, float hi) {
    unsigned long long d;
    asm("mov.b64 %0, {%1, %2};" : "=l"(d) : "f"(lo), "f"(hi));
    return d;
}
__device__ __forceinline__ void unpack2(unsigned long long v, float& lo, float& hi) {
    asm("mov.b64 {%0, %1}, %2;" : "=f"(lo), "=f"(hi) : "l"(v));
}

__global__ __launch_bounds__(THREADS, 1) void plane_validator_kernel(
        const float* __restrict__ pts, const float* __restrict__ ypred,
        const int* __restrict__ thr_ptr, float* __restrict__ out) {
    const int bid = blockIdx.x;
    const int bh  = bid >> 1;          // (b,h) pair
    const int ch  = bid & 1;           // column half
    const int t   = threadIdx.x;

    // ---------------- chamfer phase ----------------
    const float* yp = ypred + bh * 4;
    const float nx = yp[0], ny = yp[1], nz = yp[2], dpl = yp[3];
    const float inv = 1.0f / sqrtf(nx * nx + ny * ny + nz * nz);
    const float nhx = nx * inv, nhy = ny * inv, nhz = nz * inv;
    const float dh  = dpl * inv;

    const float* pb = pts + (bh >> 4) * (NPTS * 3);

    // Point-pair packed column tile (8 KB):
    //   word 2k   = { {-2rx_p0,-2rx_p1}, {-2ry_p0,-2ry_p1} }
    //   word 2k+1 = { {-2rz_p0,-2rz_p1}, { r2_p0 , r2_p1 } }   (p0=2k, p1=2k+1 local)
    // Staged scalar: thread i (local point i, pair k=i>>1, half j=i&1)
    // writes floats at sF[k*8 + c*2 + j], c in {x,y,z,r2}.
    __shared__ ulonglong2 sB[HALF];
    {
        float* sF = (float*)sB;
        int i = ch * HALF + t;                      // global point index
        float px = pb[i * 3 + 0], py = pb[i * 3 + 1], pz = pb[i * 3 + 2];
        float proj = fmaf(px, nhx, fmaf(py, nhy, fmaf(pz, nhz, dh)));
        float s = -2.0f * proj;
        float rx = fmaf(s, nhx, px);
        float ry = fmaf(s, nhy, py);
        float rz = fmaf(s, nhz, pz);
        float r2 = fmaf(rx, rx, fmaf(ry, ry, rz * rz));
        int base = (t >> 1) * 8 + (t & 1);
        sF[base + 0] = -2.0f * rx;
        sF[base + 2] = -2.0f * ry;
        sF[base + 4] = -2.0f * rz;
        sF[base + 6] = r2;
    }

    // This thread's 2 rows (plain points): coords broadcast into both f32x2 lanes
    float p2[2];
    unsigned long long ax2[2], ay2[2], az2[2];
#pragma unroll
    for (int k = 0; k < 2; k++) {
        int r = k * HALF + t;
        float px = pb[r * 3 + 0], py = pb[r * 3 + 1], pz = pb[r * 3 + 2];
        ax2[k] = pack2(px, px);
        ay2[k] = pack2(py, py);
        az2[k] = pack2(pz, pz);
        p2[k] = fmaf(px, px, fmaf(py, py, pz * pz));
    }
    __syncthreads();

    // e_{p0,p1} = {R2 - 2 p.r} for both points at once, per row.
    // 4 min accumulators (row x lane); unpack of b64 result is register-aliasing.
    float b0a = FINF, b0b = FINF, b1a = FINF, b1b = FINF;
#pragma unroll 16
    for (int k = 0; k < HALF / 2; k++) {
        ulonglong2 u0 = sB[2 * k];       // {xx, yy}
        ulonglong2 u1 = sB[2 * k + 1];   // {zz, rr}
        unsigned long long e0 = fma2(ax2[0], u0.x,
                                fma2(ay2[0], u0.y,
                                fma2(az2[0], u1.x, u1.y)));
        unsigned long long e1 = fma2(ax2[1], u0.x,
                                fma2(ay2[1], u0.y,
                                fma2(az2[1], u1.x, u1.y)));
        float e0lo, e0hi, e1lo, e1hi;
        unpack2(e0, e0lo, e0hi);
        unpack2(e1, e1lo, e1hi);
        b0a = fminf(b0a, e0lo);
        b0b = fminf(b0b, e0hi);
        b1a = fminf(b1a, e1lo);
        b1b = fminf(b1b, e1hi);
    }
    // min(e)+p2 = min(e+p2): safe to min-combine across halves later.
    const float v0 = fminf(b0a, b0b) + p2[0];
    const float v1 = fminf(b1a, b1b) + p2[1];

    g_rowmin[bid * NPTS + t]        = v0;
    g_rowmin[bid * NPTS + HALF + t] = v1;
    __threadfence();            // each thread publishes its own stores
    __syncthreads();            // all fences done before arrival

    __shared__ int s_flag;
    if (t == 0) {
        int old = atomicAdd(&g_cnt_bh[bh], 1);
        s_flag = (old == 1);    // second arriver combines
    }
    __syncthreads();
    if (!s_flag) return;

    // ---------------- combine phase (one block per bh) ----------------
    __threadfence();            // acquire peer's published rowmins
    const int peer = bid ^ 1;
    volatile float* rm = g_rowmin;
    float pv0 = rm[peer * NPTS + t];
    float pv1 = rm[peer * NPTS + HALF + t];
    float s = fminf(v0, pv0) + fminf(v1, pv1);

#pragma unroll
    for (int o = 16; o > 0; o >>= 1)
        s += __shfl_down_sync(FULL, s, o);

    __shared__ float wsum[THREADS / 32];
    if ((t & 31) == 0) wsum[t >> 5] = s;
    __syncthreads();
    if (t == 0) {
        float tot = 0.0f;
#pragma unroll
        for (int i = 0; i < THREADS / 32; i++) tot += wsum[i];
        g_part[bh] = tot;            // raw sum of 1024 row-mins
        g_cnt_bh[bh] = 0;            // reset pair counter for next replay
        __threadfence();
        int old2 = atomicAdd(&g_cnt_fin, 1);
        s_flag = (old2 == NB * NH - 1);
        if (old2 == NB * NH - 1) g_cnt_fin = 0;   // reset for next replay
    }
    __syncthreads();
    if (!s_flag) return;

    // ---------------- finalize phase (last combiner; lanes 0..63) ----------------
    __shared__ float s_ex[8][64];   // exchange: nx,ny,nz,px,py,pz,cf,sd by sorted pos

    const int l = t;
    float v_nx = 0, v_ny = 0, v_nz = 0, v_px = 0, v_py = 0, v_pz = 0, v_cf = 0, v_sd = 0;
    int pos = l & 15, b = l >> 4;

    if (l < 64) {
        // threshold: decode int32 vs float32 bit pattern defensively
        int tv = thr_ptr[0];
        float tf = __int_as_float(tv);
        float thr = (tf >= 1e-6f && tf <= 1e9f) ? tf : (float)tv;

        const float* yq = ypred + l * 4;
        float qx = yq[0], qy = yq[1], qz = yq[2], qd = yq[3];
        float qi = 1.0f / sqrtf(qx * qx + qy * qy + qz * qz);
        v_nx = qx * qi; v_ny = qy * qi; v_nz = qz * qi;
        float qdh = qd * qi;
        v_px = -qdh * v_nx; v_py = -qdh * v_ny; v_pz = -qdh * v_nz;

        // sde = 2 * mean(row mins)   (D symmetric)
        volatile float* gp = g_part;
        v_sd = gp[l] * (2.0f / (float)NPTS);

        // group min/max over 16 lanes
        float mn = v_sd, mx = v_sd;
#pragma unroll
        for (int o = 8; o > 0; o >>= 1) {
            mn = fminf(mn, __shfl_xor_sync(FULL, mn, o, 16));
            mx = fmaxf(mx, __shfl_xor_sync(FULL, mx, o, 16));
        }
        v_cf = 1.0f - (v_sd - mn) / (mx - mn);

        // stable descending rank (== stable argsort(-cf))
        int rank = 0;
#pragma unroll
        for (int j = 0; j < NH; j++) {
            float cfj = __shfl_sync(FULL, v_cf, j, 16);
            rank += (cfj > v_cf) || (cfj == v_cf && j < pos);
        }
        int slot = b * NH + rank;
        s_ex[0][slot] = v_nx; s_ex[1][slot] = v_ny; s_ex[2][slot] = v_nz;
        s_ex[3][slot] = v_px; s_ex[4][slot] = v_py; s_ex[5][slot] = v_pz;
        s_ex[6][slot] = v_cf; s_ex[7][slot] = v_sd;
        v_cf = thr;  // carry thr across the barrier
    }
    __syncthreads();
    if (l >= 64) return;

    float thr = v_cf;
    v_nx = s_ex[0][l]; v_ny = s_ex[1][l]; v_nz = s_ex[2][l];
    v_px = s_ex[3][l]; v_py = s_ex[4][l]; v_pz = s_ex[5][l];
    v_cf = s_ex[6][l]; v_sd = s_ex[7][l];

    // sequential NMS over sorted positions, live keep bits
    int keep = (v_sd <= thr);
#pragma unroll
    for (int i = 0; i < NH; i++) {
        int   ki  = __shfl_sync(FULL, keep, i, 16);
        float inx = __shfl_sync(FULL, v_nx, i, 16);
        float iny = __shfl_sync(FULL, v_ny, i, 16);
        float inz = __shfl_sync(FULL, v_nz, i, 16);
        float dt = inx * v_nx + iny * v_ny + inz * v_nz;
        if (ki && pos > i && dt > COS_THR) keep = 0;
    }

    // stable partition destination: kept first (in order), dropped after (in order)
    unsigned ball = __ballot_sync(FULL, keep);
    unsigned seg = (ball >> (l & 16)) & 0xFFFFu;
    int kept_before = __popc(seg & ((1u << pos) - 1));
    int total_kept  = __popc(seg);
    int dest = keep ? kept_before : total_kept + (pos - kept_before);

    float* o = out + (b * NH + dest) * 8;
    float4 r0 = keep ? make_float4(v_nx, v_ny, v_nz, v_px) : make_float4(0, 0, 0, 0);
    float4 r1 = keep ? make_float4(v_py, v_pz, v_cf, v_sd) : make_float4(0, 0, 0, 0);
    ((float4*)o)[0] = r0;
    ((float4*)o)[1] = r1;
}

extern "C" void kernel_launch(void* const* d_in, const int* in_sizes, int n_in,
                              void* d_out, int out_size) {
    const float* pts = nullptr;    // 12288 elems
    const float* ypred = nullptr;  // 256 elems
    const int* thr = nullptr;      // 1 elem
    for (int i = 0; i < n_in; i++) {
        if (in_sizes[i] == NB * NPTS * 3)    pts   = (const float*)d_in[i];
        else if (in_sizes[i] == NB * NH * 4) ypred = (const float*)d_in[i];
        else if (in_sizes[i] == 1)           thr   = (const int*)d_in[i];
    }
    float* out = (float*)d_out;

    plane_validator_kernel<<<NBLOCKS, THREADS>>>(pts, ypred, thr, out);
}